// round 6
// baseline (speedup 1.0000x reference)
// AttLayer fused single-kernel, GB300 (sm_103 PTX: mma.sync tf32 + manual smem pipeline).
// out[b,d] = sum_t exp(tanh(x@W + b)·uw)_t * x[b,t,d] / (sum_t exp(...) + eps)
// R4: zero mainloop CVTs (x & W stored pre-converted to tf32 in SMEM),
//     fragment-order swizzled W layout (B frags = LDS.128, conflict-free),
//     LDG->reg->CVT->STS W pipeline, KC=32, 1 barrier per chunk (8 total).

#include <cuda_runtime.h>
#include <cstdint>
#include <math.h>

#define DEV __device__ __forceinline__

static constexpr int BATCH  = 64;
static constexpr int TLEN   = 2048;
static constexpr int DIM    = 256;
static constexpr int TILE_T = 128;
static constexpr int NTILES = TLEN / TILE_T;   // 16
static constexpr int KC     = 32;              // K per chunk
static constexpr int NCHUNK = DIM / KC;        // 8

static constexpr int XSTR   = 260;             // x row stride (floats): A-frag LDS conflict-free
static constexpr int WCHUNK_F = 256 * 32;      // 8192 floats = 32KB per W buffer

// SMEM layout (bytes)
static constexpr int SMEM_BIAS = 0;                              // 256 f
static constexpr int SMEM_UW   = 1024;                           // 256 f
static constexpr int SMEM_EP   = 2048;                           // 128*4 f
static constexpr int SMEM_WEXP = 4096;                           // 128 f
static constexpr int SMEM_FLAG = 4608;                           // int
static constexpr int SMEM_X    = 4864;
static constexpr int X_BYTES   = TILE_T * XSTR * 4;              // 133120
static constexpr int SMEM_W    = SMEM_X + X_BYTES;               // 137984
static constexpr int SMEM_TOTAL = SMEM_W + 2 * WCHUNK_F * 4;     // 203520

__device__ float g_partial[BATCH * NTILES * DIM];
__device__ float g_S[BATCH * NTILES];
__device__ int   g_cnt[BATCH];   // zero-init; reset by reducer each call

DEV uint32_t f2tf(float f) {
    uint32_t r;
    asm("cvt.rna.tf32.f32 %0, %1;" : "=r"(r) : "f"(f));
    return r;
}
DEV void mma_tf32(float* d, uint32_t a0, uint32_t a1, uint32_t a2, uint32_t a3,
                  uint32_t b0, uint32_t b1) {
    asm volatile(
        "mma.sync.aligned.m16n8k8.row.col.f32.tf32.tf32.f32 "
        "{%0,%1,%2,%3}, {%4,%5,%6,%7}, {%8,%9}, {%0,%1,%2,%3};"
        : "+f"(d[0]), "+f"(d[1]), "+f"(d[2]), "+f"(d[3])
        : "r"(a0), "r"(a1), "r"(a2), "r"(a3), "r"(b0), "r"(b1));
}

// LDG one W chunk (rows c*32..c*32+31, all 256 cols) into 4 float4 regs/thread.
DEV void ldg_wchunk(float4* rv, const float* __restrict__ W, int c, int tid) {
    const float* src = W + (size_t)c * KC * DIM;
    #pragma unroll
    for (int p = 0; p < 4; ++p) {
        int flat = p * 512 + tid;
        rv[p] = *(const float4*)(src + (size_t)(flat >> 6) * DIM + (flat & 63) * 4);
    }
}

// Store a W chunk from regs into fragment-order swizzled layout (as tf32 bits).
// Element (k, n): k = 8s+4h+tg2, n = 64q+8j+gg.
//   row = ((s*2+h)*8 + gg)*4 + tg2   (0..255)
//   col = (q*8 + j + 16*(gg&1) + 4*tg2) & 31
DEV void sts_wchunk(uint32_t* wbuf, const float4* rv, int tid) {
    #pragma unroll
    for (int p = 0; p < 4; ++p) {
        int flat = p * 512 + tid;
        int k  = flat >> 6;
        int nb = (flat & 63) * 4;
        int s   = k >> 3;
        int h   = (k >> 2) & 1;
        int tg2 = k & 3;
        int q  = nb >> 6;
        int j  = (nb >> 3) & 7;
        int g0 = nb & 7;                     // 0 or 4
        float vv[4] = {rv[p].x, rv[p].y, rv[p].z, rv[p].w};
        #pragma unroll
        for (int e = 0; e < 4; ++e) {
            int gg  = g0 + e;
            int r   = ((s * 2 + h) * 8 + gg) * 4 + tg2;
            int col = (q * 8 + j + 16 * (gg & 1) + 4 * tg2) & 31;
            wbuf[r * 32 + col] = f2tf(vv[e]);
        }
    }
}

__global__ void __launch_bounds__(512, 1)
att_fused(const float* __restrict__ x, const float* __restrict__ W,
          const float* __restrict__ bvec, const float* __restrict__ uw,
          const int* __restrict__ mask, float* __restrict__ out) {
    extern __shared__ char smem[];
    float* sf = (float*)smem;

    const int tid = threadIdx.x;
    const int wid = tid >> 5;
    const int lid = tid & 31;
    const int wm  = wid >> 2;            // 0..3 : rows wm*32..+31
    const int wn  = wid & 3;             // 0..3 : cols wn*64..+63
    const int g   = lid >> 2;            // 0..7
    const int tg  = lid & 3;             // 0..3

    const int bt = blockIdx.x;           // 0..1023
    const int b  = bt >> 4;
    const int t0 = (bt & 15) * TILE_T;

    if (tid < 256) {
        sf[SMEM_BIAS / 4 + tid] = bvec[tid];
        sf[SMEM_UW / 4 + tid]   = uw[tid];
    }

    // ---- prologue: LDG W0,W1 early; fill x tile as tf32; STS W0 ----
    float4 rw0[4], R[4];
    ldg_wchunk(rw0, W, 0, tid);
    ldg_wchunk(R,   W, 1, tid);

    const float* xrow = x + ((size_t)b * TLEN + t0) * DIM;
    float* xs = sf + SMEM_X / 4;
    #pragma unroll
    for (int rr = 0; rr < 4; ++rr) {
        float4 v[4];
        #pragma unroll
        for (int p = 0; p < 4; ++p) {
            int i = (rr * 4 + p) * 512 + tid;
            v[p] = *(const float4*)(xrow + (size_t)(i >> 6) * DIM + (i & 63) * 4);
        }
        #pragma unroll
        for (int p = 0; p < 4; ++p) {
            int i = (rr * 4 + p) * 512 + tid;
            uint4 uv;
            uv.x = f2tf(v[p].x); uv.y = f2tf(v[p].y);
            uv.z = f2tf(v[p].z); uv.w = f2tf(v[p].w);
            *(uint4*)(xs + (i >> 6) * XSTR + (i & 63) * 4) = uv;
        }
    }
    sts_wchunk((uint32_t*)(sf + SMEM_W / 4), rw0, tid);
    __syncthreads();

    // ---- mainloop ----
    float acc[2][8][4];
    #pragma unroll
    for (int i = 0; i < 2; ++i)
        #pragma unroll
        for (int j = 0; j < 8; ++j)
            #pragma unroll
            for (int r = 0; r < 4; ++r) acc[i][j][r] = 0.f;

    const uint32_t* xu = (const uint32_t*)xs;
    const int arow0 = wm * 32 + g;
    const int colb  = (wn * 8 + 16 * (g & 1) + 4 * tg) & 31;
    const int colb4 = (colb + 4) & 31;

    for (int c = 0; c < NCHUNK; ++c) {
        if (c + 1 < NCHUNK)
            sts_wchunk((uint32_t*)(sf + SMEM_W / 4 + ((c + 1) & 1) * WCHUNK_F), R, tid);
        if (c + 2 < NCHUNK)
            ldg_wchunk(R, W, c + 2, tid);

        const uint32_t* wbu = (const uint32_t*)(sf + SMEM_W / 4 + (c & 1) * WCHUNK_F);
        #pragma unroll
        for (int s = 0; s < 4; ++s) {
            uint32_t a[2][4];
            #pragma unroll
            for (int i = 0; i < 2; ++i) {
                const uint32_t* ar = xu + (arow0 + i * 16) * XSTR + c * KC + s * 8 + tg;
                a[i][0] = ar[0];
                a[i][1] = ar[8 * XSTR];
                a[i][2] = ar[4];
                a[i][3] = ar[8 * XSTR + 4];
            }
            uint32_t bfr[8][2];
            #pragma unroll
            for (int h = 0; h < 2; ++h) {
                int r = ((s * 2 + h) * 8 + g) * 4 + tg;
                uint4 v0 = *(const uint4*)(wbu + r * 32 + colb);
                uint4 v1 = *(const uint4*)(wbu + r * 32 + colb4);
                bfr[0][h] = v0.x; bfr[1][h] = v0.y; bfr[2][h] = v0.z; bfr[3][h] = v0.w;
                bfr[4][h] = v1.x; bfr[5][h] = v1.y; bfr[6][h] = v1.z; bfr[7][h] = v1.w;
            }
            #pragma unroll
            for (int i = 0; i < 2; ++i)
                #pragma unroll
                for (int j = 0; j < 8; ++j)
                    mma_tf32(acc[i][j], a[i][0], a[i][1], a[i][2], a[i][3],
                             bfr[j][0], bfr[j][1]);
        }
        __syncthreads();
    }

    // ---- epilogue 1: eij partials ----
    {
        const float* sBias = sf + SMEM_BIAS / 4;
        const float* sUw   = sf + SMEM_UW / 4;
        float* epart       = sf + SMEM_EP / 4;
        #pragma unroll
        for (int i = 0; i < 2; ++i) {
            float rs0 = 0.f, rs1 = 0.f;
            #pragma unroll
            for (int j = 0; j < 8; ++j) {
                const int c0 = wn * 64 + j * 8 + 2 * tg;
                const float b0 = sBias[c0], b1 = sBias[c0 + 1];
                const float u0 = sUw[c0],   u1 = sUw[c0 + 1];
                rs0 += tanhf(acc[i][j][0] + b0) * u0 + tanhf(acc[i][j][1] + b1) * u1;
                rs1 += tanhf(acc[i][j][2] + b0) * u0 + tanhf(acc[i][j][3] + b1) * u1;
            }
            rs0 += __shfl_xor_sync(0xFFFFFFFFu, rs0, 1);
            rs0 += __shfl_xor_sync(0xFFFFFFFFu, rs0, 2);
            rs1 += __shfl_xor_sync(0xFFFFFFFFu, rs1, 1);
            rs1 += __shfl_xor_sync(0xFFFFFFFFu, rs1, 2);
            if (tg == 0) {
                const int r = wm * 32 + i * 16 + g;
                epart[r * 4 + wn]       = rs0;
                epart[(r + 8) * 4 + wn] = rs1;
            }
        }
    }
    __syncthreads();

    // ---- epilogue 2: softmax-numerator weights ----
    float* sWexp = sf + SMEM_WEXP / 4;
    if (tid < TILE_T) {
        const float* epart = sf + SMEM_EP / 4;
        float e = epart[tid * 4 + 0] + epart[tid * 4 + 1] +
                  epart[tid * 4 + 2] + epart[tid * 4 + 3];
        sWexp[tid] = expf(e) * (float)mask[(size_t)b * TLEN + t0 + tid];
    }
    __syncthreads();

    if (tid == 0) {
        float s = 0.f;
        #pragma unroll 8
        for (int m = 0; m < TILE_T; ++m) s += sWexp[m];
        g_S[bt] = s;
    }

    // ---- epilogue 3: weighted column sum from resident x tile (tf32 values) ----
    if (tid < DIM) {
        float a0 = 0.f;
        #pragma unroll 8
        for (int m = 0; m < TILE_T; ++m)
            a0 = fmaf(sWexp[m], xs[m * XSTR + tid], a0);
        g_partial[(size_t)bt * DIM + tid] = a0;
    }

    // ---- fused tail: last CTA of each batch reduces (deterministic order) ----
    __threadfence();
    __syncthreads();
    int* sflag = (int*)(smem + SMEM_FLAG);
    if (tid == 0) {
        int old = atomicAdd(&g_cnt[b], 1);
        *sflag = (old == NTILES - 1);
    }
    __syncthreads();
    if (*sflag) {
        __threadfence();   // acquire: see all tiles' partials
        if (tid < DIM) {
            float s = 0.f, p = 0.f;
            #pragma unroll
            for (int t = 0; t < NTILES; ++t) {
                p += g_partial[(size_t)(b * NTILES + t) * DIM + tid];
                s += g_S[b * NTILES + t];
            }
            out[b * DIM + tid] = p / (s + 1e-7f);
        }
        if (tid == 0) g_cnt[b] = 0;   // reset for next graph replay
    }
}

extern "C" void kernel_launch(void* const* d_in, const int* in_sizes, int n_in,
                              void* d_out, int out_size) {
    const float* x    = (const float*)d_in[0];
    const float* W    = (const float*)d_in[1];
    const float* bvec = (const float*)d_in[2];
    const float* uw   = (const float*)d_in[3];
    const int*   mask = (const int*)d_in[4];
    float* out = (float*)d_out;

    cudaFuncSetAttribute(att_fused, cudaFuncAttributeMaxDynamicSharedMemorySize,
                         SMEM_TOTAL);
    att_fused<<<BATCH * NTILES, 512, SMEM_TOTAL>>>(x, W, bvec, uw, mask, out);
}

// round 8
// speedup vs baseline: 1.1769x; 1.1769x over previous
// AttLayer fused single-kernel, GB300 (sm_103 PTX: mma.sync tf32 + cp.async).
// out[b,d] = sum_t exp(tanh(x@W + b)·uw)_t * x[b,t,d] / (sum_t exp(...) + eps)
// R6: TILE_T=64 -> ~101.5KB SMEM -> 2 CTAs/SM (32 warps) for latency hiding.
//     Warp tile M=16,N=64 (acc=32 regs), __launch_bounds__(512,2) (<=64 regs).
//     x stored pre-converted to tf32 (no A-side CVTs); R2-proven cp.async W pipe.

#include <cuda_runtime.h>
#include <cstdint>
#include <math.h>

#define DEV __device__ __forceinline__

static constexpr int BATCH  = 64;
static constexpr int TLEN   = 2048;
static constexpr int DIM    = 256;
static constexpr int TILE_T = 64;
static constexpr int NTILES = TLEN / TILE_T;   // 32
static constexpr int KC     = 16;              // K per chunk
static constexpr int NCHUNK = DIM / KC;        // 16

static constexpr int XSTR   = 260;             // A-frag LDS conflict-free (260 % 32 == 4)
static constexpr int WSTR   = 264;             // B-frag LDS conflict-free (264 % 32 == 8)

// SMEM layout (bytes)
static constexpr int SMEM_BIAS = 0;                               // 256 f
static constexpr int SMEM_UW   = 1024;                            // 256 f
static constexpr int SMEM_EP   = 2048;                            // 64*4 f
static constexpr int SMEM_WEXP = 3072;                            // 64 f
static constexpr int SMEM_FLAG = 3328;                            // int
static constexpr int SMEM_X    = 3584;
static constexpr int X_BYTES   = TILE_T * XSTR * 4;               // 66560
static constexpr int SMEM_W    = SMEM_X + X_BYTES;                // 70144
static constexpr int W_CHUNK_B = KC * WSTR * 4;                   // 16896
static constexpr int SMEM_TOTAL = SMEM_W + 2 * W_CHUNK_B;         // 103936 (~101.5KB)

__device__ float g_partial[BATCH * NTILES * DIM];
__device__ float g_S[BATCH * NTILES];
__device__ int   g_cnt[BATCH];   // zero-init; reset by reducer each call

DEV uint32_t smem_u32(const void* p) {
    uint32_t a;
    asm("{ .reg .u64 t; cvta.to.shared.u64 t, %1; cvt.u32.u64 %0, t; }"
        : "=r"(a) : "l"(p));
    return a;
}
DEV void cp16(uint32_t saddr, const void* g) {
    asm volatile("cp.async.cg.shared.global [%0], [%1], 16;"
                 :: "r"(saddr), "l"(g) : "memory");
}
DEV void cp_commit() { asm volatile("cp.async.commit_group;" ::: "memory"); }
template <int N> DEV void cp_wait() {
    asm volatile("cp.async.wait_group %0;" :: "n"(N) : "memory");
}
DEV uint32_t f2tf(float f) {
    uint32_t r;
    asm("cvt.rna.tf32.f32 %0, %1;" : "=r"(r) : "f"(f));
    return r;
}
DEV void mma_tf32(float* d, uint32_t a0, uint32_t a1, uint32_t a2, uint32_t a3,
                  uint32_t b0, uint32_t b1) {
    asm volatile(
        "mma.sync.aligned.m16n8k8.row.col.f32.tf32.tf32.f32 "
        "{%0,%1,%2,%3}, {%4,%5,%6,%7}, {%8,%9}, {%0,%1,%2,%3};"
        : "+f"(d[0]), "+f"(d[1]), "+f"(d[2]), "+f"(d[3])
        : "r"(a0), "r"(a1), "r"(a2), "r"(a3), "r"(b0), "r"(b1));
}

DEV void load_w_chunk(uint32_t sb, const float* __restrict__ W, int c, int buf, int tid) {
    // W rows c*16 .. c*16+15, all 256 cols -> ring buffer `buf`. 1024 float4 / 512 thr.
    const float* wsrc = W + (size_t)c * KC * DIM;
    const uint32_t dst = sb + (uint32_t)(SMEM_W + buf * W_CHUNK_B);
    #pragma unroll
    for (int r = 0; r < 2; ++r) {
        int i = tid + r * 512;
        int k = i >> 6, n0 = (i & 63) * 4;
        cp16(dst + (uint32_t)(k * WSTR + n0) * 4, wsrc + (size_t)k * DIM + n0);
    }
    cp_commit();
}

__global__ void __launch_bounds__(512, 2)
att_fused(const float* __restrict__ x, const float* __restrict__ W,
          const float* __restrict__ bvec, const float* __restrict__ uw,
          const int* __restrict__ mask, float* __restrict__ out) {
    extern __shared__ char smem[];
    float* sf = (float*)smem;
    const uint32_t sb = smem_u32(smem);

    const int tid = threadIdx.x;
    const int wid = tid >> 5;
    const int lid = tid & 31;
    const int wm  = wid >> 2;            // 0..3 : rows wm*16..+15
    const int wn  = wid & 3;             // 0..3 : cols wn*64..+63
    const int g   = lid >> 2;            // 0..7
    const int tg  = lid & 3;             // 0..3

    const int bt = blockIdx.x;           // 0..2047
    const int b  = bt >> 5;
    const int t0 = (bt & 31) * TILE_T;

    if (tid < 256) {
        sf[SMEM_BIAS / 4 + tid] = bvec[tid];
        sf[SMEM_UW / 4 + tid]   = uw[tid];
    }

    // ---- prologue: cp.async W0,W1; x tile LDG->CVT->STS (tf32 bits) ----
    load_w_chunk(sb, W, 0, 0, tid);
    load_w_chunk(sb, W, 1, 1, tid);

    const float* xrow = x + ((size_t)b * TLEN + t0) * DIM;
    float* xs = sf + SMEM_X / 4;
    #pragma unroll
    for (int r = 0; r < 8; ++r) {        // 64*64=4096 float4 / 512 thr = 8 each
        int i = r * 512 + tid;
        int m = i >> 6, d0 = (i & 63) * 4;
        float4 v = *(const float4*)(xrow + (size_t)m * DIM + d0);
        uint4 uv;
        uv.x = f2tf(v.x); uv.y = f2tf(v.y); uv.z = f2tf(v.z); uv.w = f2tf(v.w);
        *(uint4*)(xs + m * XSTR + d0) = uv;
    }
    cp_wait<1>();                        // W0 ready
    __syncthreads();

    // ---- mainloop: warp tile M=16, N=64 ----
    float acc[8][4];
    #pragma unroll
    for (int j = 0; j < 8; ++j)
        #pragma unroll
        for (int r = 0; r < 4; ++r) acc[j][r] = 0.f;

    const uint32_t* xu = (const uint32_t*)xs;
    const int arow = wm * 16 + g;

    for (int c = 0; c < NCHUNK; ++c) {
        const float* wb = sf + (SMEM_W + (c & 1) * W_CHUNK_B) / 4;
        #pragma unroll
        for (int s = 0; s < 2; ++s) {    // KC=16 -> 2 k8 steps
            const int kc0 = s * 8 + tg;
            const uint32_t* ar = xu + arow * XSTR + c * KC + kc0;
            uint32_t a0 = ar[0];
            uint32_t a1 = ar[8 * XSTR];
            uint32_t a2 = ar[4];
            uint32_t a3 = ar[8 * XSTR + 4];
            uint32_t bfr[8][2];
            const float* br = wb + kc0 * WSTR + wn * 64 + g;
            #pragma unroll
            for (int j = 0; j < 8; ++j) {
                bfr[j][0] = f2tf(br[j * 8]);
                bfr[j][1] = f2tf(br[4 * WSTR + j * 8]);
            }
            #pragma unroll
            for (int j = 0; j < 8; ++j)
                mma_tf32(acc[j], a0, a1, a2, a3, bfr[j][0], bfr[j][1]);
        }
        __syncthreads();                 // done reading buf c&1
        if (c + 2 < NCHUNK) {
            load_w_chunk(sb, W, c + 2, c & 1, tid);
            cp_wait<1>();                // chunk c+1 ready
            __syncthreads();
        } else if (c + 1 < NCHUNK) {
            cp_wait<0>();
            __syncthreads();
        }
    }

    // ---- epilogue 1: eij partials ----
    {
        const float* sBias = sf + SMEM_BIAS / 4;
        const float* sUw   = sf + SMEM_UW / 4;
        float* epart       = sf + SMEM_EP / 4;
        float rs0 = 0.f, rs1 = 0.f;
        #pragma unroll
        for (int j = 0; j < 8; ++j) {
            const int c0 = wn * 64 + j * 8 + 2 * tg;
            const float b0 = sBias[c0], b1 = sBias[c0 + 1];
            const float u0 = sUw[c0],   u1 = sUw[c0 + 1];
            rs0 += tanhf(acc[j][0] + b0) * u0 + tanhf(acc[j][1] + b1) * u1;
            rs1 += tanhf(acc[j][2] + b0) * u0 + tanhf(acc[j][3] + b1) * u1;
        }
        rs0 += __shfl_xor_sync(0xFFFFFFFFu, rs0, 1);
        rs0 += __shfl_xor_sync(0xFFFFFFFFu, rs0, 2);
        rs1 += __shfl_xor_sync(0xFFFFFFFFu, rs1, 1);
        rs1 += __shfl_xor_sync(0xFFFFFFFFu, rs1, 2);
        if (tg == 0) {
            const int r = wm * 16 + g;
            epart[r * 4 + wn]       = rs0;
            epart[(r + 8) * 4 + wn] = rs1;
        }
    }
    __syncthreads();

    // ---- epilogue 2: softmax-numerator weights ----
    float* sWexp = sf + SMEM_WEXP / 4;
    if (tid < TILE_T) {
        const float* epart = sf + SMEM_EP / 4;
        float e = epart[tid * 4 + 0] + epart[tid * 4 + 1] +
                  epart[tid * 4 + 2] + epart[tid * 4 + 3];
        sWexp[tid] = expf(e) * (float)mask[(size_t)b * TLEN + t0 + tid];
    }
    __syncthreads();

    if (tid == 0) {
        float s = 0.f;
        #pragma unroll 8
        for (int m = 0; m < TILE_T; ++m) s += sWexp[m];
        g_S[bt] = s;
    }

    // ---- epilogue 3: weighted column sum from resident x tile (tf32 values) ----
    if (tid < DIM) {
        float a0 = 0.f;
        #pragma unroll 8
        for (int m = 0; m < TILE_T; ++m)
            a0 = fmaf(sWexp[m], xs[m * XSTR + tid], a0);
        g_partial[(size_t)bt * DIM + tid] = a0;
    }

    // ---- fused tail: last CTA of each batch reduces (deterministic order) ----
    __threadfence();
    __syncthreads();
    int* sflag = (int*)(smem + SMEM_FLAG);
    if (tid == 0) {
        int old = atomicAdd(&g_cnt[b], 1);
        *sflag = (old == NTILES - 1);
    }
    __syncthreads();
    if (*sflag) {
        __threadfence();   // acquire: see all tiles' partials
        if (tid < DIM) {
            float s = 0.f, p = 0.f;
            #pragma unroll
            for (int t = 0; t < NTILES; ++t) {
                p += g_partial[(size_t)(b * NTILES + t) * DIM + tid];
                s += g_S[b * NTILES + t];
            }
            out[b * DIM + tid] = p / (s + 1e-7f);
        }
        if (tid == 0) g_cnt[b] = 0;   // reset for next graph replay
    }
}

extern "C" void kernel_launch(void* const* d_in, const int* in_sizes, int n_in,
                              void* d_out, int out_size) {
    const float* x    = (const float*)d_in[0];
    const float* W    = (const float*)d_in[1];
    const float* bvec = (const float*)d_in[2];
    const float* uw   = (const float*)d_in[3];
    const int*   mask = (const int*)d_in[4];
    float* out = (float*)d_out;

    cudaFuncSetAttribute(att_fused, cudaFuncAttributeMaxDynamicSharedMemorySize,
                         SMEM_TOTAL);
    att_fused<<<BATCH * NTILES, 512, SMEM_TOTAL>>>(x, W, bvec, uw, mask, out);
}

// round 9
// speedup vs baseline: 1.3023x; 1.1066x over previous
// AttLayer fused, GB300 (sm_103 PTX: mma.sync tf32 + cp.async).
// out[b,d] = sum_t exp(tanh(x@W + b)·uw)_t * x[b,t,d] / (sum_t exp(...) + eps)
// R8: W pre-converted to tf32 AND pre-swizzled into fragment-order global layout
//     by a tiny prep kernel (runs once per call, amortized over 1024 CTAs).
//     Mainloop has ZERO cvt instructions; B fragments are 4x LDS.128 per k8-step,
//     bank-conflict-free; W chunks stream via linear 32KB cp.async copies.
//     TILE_T=128, warp tile M=32 N=64 (best MMA-per-LDS ratio).

#include <cuda_runtime.h>
#include <cstdint>
#include <math.h>

#define DEV __device__ __forceinline__

static constexpr int BATCH  = 64;
static constexpr int TLEN   = 2048;
static constexpr int DIM    = 256;
static constexpr int TILE_T = 128;
static constexpr int NTILES = TLEN / TILE_T;   // 16
static constexpr int KC     = 32;              // K per chunk
static constexpr int NCHUNK = DIM / KC;        // 8
static constexpr int WCHUNK_F = 256 * 32;      // 8192 words = 32KB per chunk

static constexpr int XSTR   = 260;             // A-frag LDS conflict-free

// SMEM layout (bytes)
static constexpr int SMEM_BIAS = 0;                              // 256 f
static constexpr int SMEM_UW   = 1024;                           // 256 f
static constexpr int SMEM_EP   = 2048;                           // 128*4 f
static constexpr int SMEM_WEXP = 4096;                           // 128 f
static constexpr int SMEM_FLAG = 4608;                           // int
static constexpr int SMEM_X    = 4864;
static constexpr int X_BYTES   = TILE_T * XSTR * 4;              // 133120
static constexpr int SMEM_W    = SMEM_X + X_BYTES;               // 137984
static constexpr int SMEM_TOTAL = SMEM_W + 2 * WCHUNK_F * 4;     // 203520

__device__ uint32_t g_Wtf[DIM * DIM];          // fragment-order tf32 W (256KB)
__device__ float g_partial[BATCH * NTILES * DIM];
__device__ float g_S[BATCH * NTILES];
__device__ int   g_cnt[BATCH];                 // zero-init; reset by reducer

DEV uint32_t smem_u32(const void* p) {
    uint32_t a;
    asm("{ .reg .u64 t; cvta.to.shared.u64 t, %1; cvt.u32.u64 %0, t; }"
        : "=r"(a) : "l"(p));
    return a;
}
DEV void cp16(uint32_t saddr, const void* g) {
    asm volatile("cp.async.cg.shared.global [%0], [%1], 16;"
                 :: "r"(saddr), "l"(g) : "memory");
}
DEV void cp_commit() { asm volatile("cp.async.commit_group;" ::: "memory"); }
template <int N> DEV void cp_wait() {
    asm volatile("cp.async.wait_group %0;" :: "n"(N) : "memory");
}
DEV uint32_t f2tf(float f) {
    uint32_t r;
    asm("cvt.rna.tf32.f32 %0, %1;" : "=r"(r) : "f"(f));
    return r;
}
DEV void mma_tf32(float* d, uint32_t a0, uint32_t a1, uint32_t a2, uint32_t a3,
                  uint32_t b0, uint32_t b1) {
    asm volatile(
        "mma.sync.aligned.m16n8k8.row.col.f32.tf32.tf32.f32 "
        "{%0,%1,%2,%3}, {%4,%5,%6,%7}, {%8,%9}, {%0,%1,%2,%3};"
        : "+f"(d[0]), "+f"(d[1]), "+f"(d[2]), "+f"(d[3])
        : "r"(a0), "r"(a1), "r"(a2), "r"(a3), "r"(b0), "r"(b1));
}

// ---- prep: W[k][n] fp32 -> g_Wtf fragment-order tf32 ----
// chunk c = k>>5; kk=k&31: s=kk>>3, h=(kk>>2)&1, tg2=kk&3
// n: q=n>>6, j=(n>>3)&7, gg=n&7
// row = ((s*2+h)*8+gg)*4 + tg2 ; col = (q*8 + j + 16*(gg&1) + 4*tg2) & 31
__global__ void __launch_bounds__(512, 4)
w_prep(const float* __restrict__ W) {
    int i = blockIdx.x * 512 + threadIdx.x;    // 0..65535
    int k = i >> 8, n = i & 255;
    int c = k >> 5, kk = k & 31;
    int s = kk >> 3, h = (kk >> 2) & 1, tg2 = kk & 3;
    int q = n >> 6, j = (n >> 3) & 7, gg = n & 7;
    int r   = ((s * 2 + h) * 8 + gg) * 4 + tg2;
    int col = (q * 8 + j + 16 * (gg & 1) + 4 * tg2) & 31;
    g_Wtf[c * WCHUNK_F + r * 32 + col] = f2tf(W[k * DIM + n]);
}

DEV void load_w_chunk(uint32_t sb, int c, int buf, int tid) {
    // linear 32KB copy: 2048 uint4 / 512 threads = 4 each
    const uint32_t* src = g_Wtf + c * WCHUNK_F;
    const uint32_t dst = sb + (uint32_t)(SMEM_W + buf * WCHUNK_F * 4);
    #pragma unroll
    for (int r = 0; r < 4; ++r) {
        int i = tid + r * 512;
        cp16(dst + (uint32_t)i * 16, src + i * 4);
    }
    cp_commit();
}

__global__ void __launch_bounds__(512, 1)
att_fused(const float* __restrict__ x,
          const float* __restrict__ bvec, const float* __restrict__ uw,
          const int* __restrict__ mask, float* __restrict__ out) {
    extern __shared__ char smem[];
    float* sf = (float*)smem;
    const uint32_t sb = smem_u32(smem);

    const int tid = threadIdx.x;
    const int wid = tid >> 5;
    const int lid = tid & 31;
    const int wm  = wid >> 2;            // 0..3 : rows wm*32..+31
    const int wn  = wid & 3;             // 0..3 : cols wn*64..+63
    const int g   = lid >> 2;            // 0..7
    const int tg  = lid & 3;             // 0..3

    const int bt = blockIdx.x;           // 0..1023
    const int b  = bt >> 4;
    const int t0 = (bt & 15) * TILE_T;

    if (tid < 256) {
        sf[SMEM_BIAS / 4 + tid] = bvec[tid];
        sf[SMEM_UW / 4 + tid]   = uw[tid];
    }

    // ---- prologue: cp.async W0 | x fill (LDG->CVT->STS) | cp.async W1 ----
    load_w_chunk(sb, 0, 0, tid);

    const float* xrow = x + ((size_t)b * TLEN + t0) * DIM;
    float* xs = sf + SMEM_X / 4;
    #pragma unroll
    for (int r = 0; r < 16; ++r) {       // 128*64=8192 float4 / 512 thr
        int i = r * 512 + tid;
        int m = i >> 6, d0 = (i & 63) * 4;
        float4 v = *(const float4*)(xrow + (size_t)m * DIM + d0);
        uint4 uv;
        uv.x = f2tf(v.x); uv.y = f2tf(v.y); uv.z = f2tf(v.z); uv.w = f2tf(v.w);
        *(uint4*)(xs + m * XSTR + d0) = uv;
    }
    load_w_chunk(sb, 1, 1, tid);
    cp_wait<1>();                        // W0 ready
    __syncthreads();

    // ---- mainloop: warp tile M=32, N=64; zero CVTs ----
    float acc[2][8][4];
    #pragma unroll
    for (int i = 0; i < 2; ++i)
        #pragma unroll
        for (int j = 0; j < 8; ++j)
            #pragma unroll
            for (int r = 0; r < 4; ++r) acc[i][j][r] = 0.f;

    const uint32_t* xu = (const uint32_t*)xs;
    const int arow0 = wm * 32 + g;
    const int colb  = (wn * 8 + 16 * (g & 1) + 4 * tg) & 31;
    const int colb4 = (colb + 4) & 31;

    for (int c = 0; c < NCHUNK; ++c) {
        const uint32_t* wbu =
            (const uint32_t*)(sf + SMEM_W / 4 + (c & 1) * WCHUNK_F);
        #pragma unroll
        for (int s = 0; s < 4; ++s) {
            uint32_t a[2][4];
            #pragma unroll
            for (int i = 0; i < 2; ++i) {
                const uint32_t* ar = xu + (arow0 + i * 16) * XSTR + c * KC + s * 8 + tg;
                a[i][0] = ar[0];
                a[i][1] = ar[8 * XSTR];
                a[i][2] = ar[4];
                a[i][3] = ar[8 * XSTR + 4];
            }
            uint32_t bfr[8][2];
            #pragma unroll
            for (int h = 0; h < 2; ++h) {
                int r = ((s * 2 + h) * 8 + g) * 4 + tg;
                uint4 v0 = *(const uint4*)(wbu + r * 32 + colb);
                uint4 v1 = *(const uint4*)(wbu + r * 32 + colb4);
                bfr[0][h] = v0.x; bfr[1][h] = v0.y; bfr[2][h] = v0.z; bfr[3][h] = v0.w;
                bfr[4][h] = v1.x; bfr[5][h] = v1.y; bfr[6][h] = v1.z; bfr[7][h] = v1.w;
            }
            #pragma unroll
            for (int i = 0; i < 2; ++i)
                #pragma unroll
                for (int j = 0; j < 8; ++j)
                    mma_tf32(acc[i][j], a[i][0], a[i][1], a[i][2], a[i][3],
                             bfr[j][0], bfr[j][1]);
        }
        __syncthreads();                 // done reading buf c&1
        if (c + 2 < NCHUNK) {
            load_w_chunk(sb, c + 2, c & 1, tid);
        }
        if (c + 1 < NCHUNK) {
            if (c + 2 < NCHUNK) cp_wait<1>(); else cp_wait<0>();
            __syncthreads();
        }
    }

    // ---- epilogue 1: eij partials ----
    {
        const float* sBias = sf + SMEM_BIAS / 4;
        const float* sUw   = sf + SMEM_UW / 4;
        float* epart       = sf + SMEM_EP / 4;
        #pragma unroll
        for (int i = 0; i < 2; ++i) {
            float rs0 = 0.f, rs1 = 0.f;
            #pragma unroll
            for (int j = 0; j < 8; ++j) {
                const int c0 = wn * 64 + j * 8 + 2 * tg;
                const float b0 = sBias[c0], b1 = sBias[c0 + 1];
                const float u0 = sUw[c0],   u1 = sUw[c0 + 1];
                rs0 += tanhf(acc[i][j][0] + b0) * u0 + tanhf(acc[i][j][1] + b1) * u1;
                rs1 += tanhf(acc[i][j][2] + b0) * u0 + tanhf(acc[i][j][3] + b1) * u1;
            }
            rs0 += __shfl_xor_sync(0xFFFFFFFFu, rs0, 1);
            rs0 += __shfl_xor_sync(0xFFFFFFFFu, rs0, 2);
            rs1 += __shfl_xor_sync(0xFFFFFFFFu, rs1, 1);
            rs1 += __shfl_xor_sync(0xFFFFFFFFu, rs1, 2);
            if (tg == 0) {
                const int r = wm * 32 + i * 16 + g;
                epart[r * 4 + wn]       = rs0;
                epart[(r + 8) * 4 + wn] = rs1;
            }
        }
    }
    __syncthreads();

    // ---- epilogue 2: softmax-numerator weights ----
    float* sWexp = sf + SMEM_WEXP / 4;
    if (tid < TILE_T) {
        const float* epart = sf + SMEM_EP / 4;
        float e = epart[tid * 4 + 0] + epart[tid * 4 + 1] +
                  epart[tid * 4 + 2] + epart[tid * 4 + 3];
        sWexp[tid] = expf(e) * (float)mask[(size_t)b * TLEN + t0 + tid];
    }
    __syncthreads();

    if (tid == 0) {
        float s = 0.f;
        #pragma unroll 8
        for (int m = 0; m < TILE_T; ++m) s += sWexp[m];
        g_S[bt] = s;
    }

    // ---- epilogue 3: weighted column sum from resident x tile (tf32 values) ----
    if (tid < DIM) {
        float a0 = 0.f;
        #pragma unroll 8
        for (int m = 0; m < TILE_T; ++m)
            a0 = fmaf(sWexp[m], xs[m * XSTR + tid], a0);
        g_partial[(size_t)bt * DIM + tid] = a0;
    }

    // ---- fused tail: last CTA of each batch reduces (deterministic order) ----
    __threadfence();
    __syncthreads();
    int* sflag = (int*)(smem + SMEM_FLAG);
    if (tid == 0) {
        int old = atomicAdd(&g_cnt[b], 1);
        *sflag = (old == NTILES - 1);
    }
    __syncthreads();
    if (*sflag) {
        __threadfence();   // acquire: see all tiles' partials
        if (tid < DIM) {
            float s = 0.f, p = 0.f;
            #pragma unroll
            for (int t = 0; t < NTILES; ++t) {
                p += g_partial[(size_t)(b * NTILES + t) * DIM + tid];
                s += g_S[b * NTILES + t];
            }
            out[b * DIM + tid] = p / (s + 1e-7f);
        }
        if (tid == 0) g_cnt[b] = 0;   // reset for next graph replay
    }
}

extern "C" void kernel_launch(void* const* d_in, const int* in_sizes, int n_in,
                              void* d_out, int out_size) {
    const float* x    = (const float*)d_in[0];
    const float* W    = (const float*)d_in[1];
    const float* bvec = (const float*)d_in[2];
    const float* uw   = (const float*)d_in[3];
    const int*   mask = (const int*)d_in[4];
    float* out = (float*)d_out;

    w_prep<<<DIM * DIM / 512, 512>>>(W);
    cudaFuncSetAttribute(att_fused, cudaFuncAttributeMaxDynamicSharedMemorySize,
                         SMEM_TOTAL);
    att_fused<<<BATCH * NTILES, 512, SMEM_TOTAL>>>(x, bvec, uw, mask, out);
}